// round 11
// baseline (speedup 1.0000x reference)
#include <cuda_runtime.h>
#include <cuda_fp16.h>
#include <math.h>
#include <stdint.h>

#define NB 8192
#define ND 256
#define MAXC 64    // per-row candidate capacity (expected ~10, max ~35)

__device__ unsigned char d_embq[(size_t)NB * ND];   // int8 quantized, 2 MB
__device__ unsigned int d_maxabs;
__device__ unsigned int d_rmin[NB];
__device__ unsigned int d_rmax[NB];
__device__ unsigned int d_cand[(size_t)NB * MAXC];  // bit31=neg | j<<16 | f16bits(s)
__device__ int d_cnt[NB];
__device__ float d_row_term[NB];
__device__ float d_row_valid[NB];

// ---------------- helpers ----------------
__device__ __forceinline__ uint32_t smem_u32(const void* p) {
    uint32_t a;
    asm("{ .reg .u64 t; cvta.to.shared.u64 t, %1; cvt.u32.u64 %0, t; }" : "=r"(a) : "l"(p));
    return a;
}
__device__ __forceinline__ void cp16(uint32_t dst, const void* src) {
    asm volatile("cp.async.cg.shared.global [%0], [%1], 16;" :: "r"(dst), "l"(src) : "memory");
}
__device__ __forceinline__ void cp_commit() {
    asm volatile("cp.async.commit_group;" ::: "memory");
}
template <int N>
__device__ __forceinline__ void cp_wait() {
    asm volatile("cp.async.wait_group %0;" :: "n"(N) : "memory");
}
__device__ __forceinline__ void ldsm4(uint32_t r[4], uint32_t addr) {
    asm volatile("ldmatrix.sync.aligned.m8n8.x4.shared.b16 {%0,%1,%2,%3}, [%4];"
                 : "=r"(r[0]), "=r"(r[1]), "=r"(r[2]), "=r"(r[3]) : "r"(addr));
}
__device__ __forceinline__ void mma32s8(int c[4], const uint32_t a[4], uint32_t b0, uint32_t b1) {
    asm volatile(
        "mma.sync.aligned.m16n8k32.row.col.s32.s8.s8.s32 "
        "{%0,%1,%2,%3}, {%4,%5,%6,%7}, {%8,%9}, {%0,%1,%2,%3};"
        : "+r"(c[0]), "+r"(c[1]), "+r"(c[2]), "+r"(c[3])
        : "r"(a[0]), "r"(a[1]), "r"(a[2]), "r"(a[3]), "r"(b0), "r"(b1));
}
__device__ __forceinline__ float ex2(float x) {
    float r;
    asm("ex2.approx.f32 %0, %1;" : "=f"(r) : "f"(x));
    return r;
}
__device__ __forceinline__ unsigned int encf(float f) {
    unsigned int u = __float_as_uint(f);
    return (u >> 31) ? ~u : (u | 0x80000000u);
}
__device__ __forceinline__ float decf(unsigned int u) {
    return __uint_as_float((u >> 31) ? (u ^ 0x80000000u) : ~u);
}
__device__ __forceinline__ void push_cand(int row, int j, float s, bool isneg) {
    unsigned int key = (isneg ? 0x80000000u : 0u) | ((unsigned)j << 16)
                     | (unsigned)__half_as_ushort(__float2half_rn(s));
    int p = atomicAdd(&d_cnt[row], 1);
    if (p < MAXC) d_cand[(size_t)row * MAXC + p] = key;
}

// ---------------------------------------------------------------------------
// Prep: global max|e| -> int8 quantize; init arrays.
// ---------------------------------------------------------------------------
__global__ void __launch_bounds__(256) prep_misc(const int* __restrict__ labels) {
    int i = blockIdx.x * 256 + threadIdx.x;
    d_rmin[i] = 0xFFFFFFFFu;
    d_rmax[i] = 0u;
    d_cnt[i] = 0;
    if (i == 0) d_maxabs = 0u;
}
__global__ void __launch_bounds__(256) prep_max(const float* __restrict__ emb) {
    int i = blockIdx.x * 256 + threadIdx.x;  // 8 floats per thread
    float4 a = ((const float4*)emb)[i * 2];
    float4 b = ((const float4*)emb)[i * 2 + 1];
    float m = fmaxf(fmaxf(fmaxf(fabsf(a.x), fabsf(a.y)), fmaxf(fabsf(a.z), fabsf(a.w))),
                    fmaxf(fmaxf(fabsf(b.x), fabsf(b.y)), fmaxf(fabsf(b.z), fabsf(b.w))));
#pragma unroll
    for (int o = 16; o > 0; o >>= 1) m = fmaxf(m, __shfl_xor_sync(0xFFFFFFFFu, m, o));
    if ((threadIdx.x & 31) == 0) atomicMax(&d_maxabs, __float_as_uint(m));  // positive floats
}
__global__ void __launch_bounds__(256) prep_quant(const float* __restrict__ emb) {
    int i = blockIdx.x * 256 + threadIdx.x;  // 8 elements per thread
    float S = 127.0f / __uint_as_float(d_maxabs);
    float4 a = ((const float4*)emb)[i * 2];
    float4 b = ((const float4*)emb)[i * 2 + 1];
    float f[8] = {a.x, a.y, a.z, a.w, b.x, b.y, b.z, b.w};
    unsigned int lo = 0, hi = 0;
#pragma unroll
    for (int e = 0; e < 4; e++) {
        int q = max(-127, min(127, __float2int_rn(f[e] * S)));
        lo |= ((unsigned)q & 0xFFu) << (e * 8);
    }
#pragma unroll
    for (int e = 0; e < 4; e++) {
        int q = max(-127, min(127, __float2int_rn(f[4 + e] * S)));
        hi |= ((unsigned)q & 0xFFu) << (e * 8);
    }
    ((uint2*)d_embq)[i] = make_uint2(lo, hi);
}

// ---------------------------------------------------------------------------
// GEMM: int8 mma.sync m16n8k32, triangular 128x128 tiles, 8 warps of 64x32,
// 2 stages of BK=128 int8 (full K in smem after prologue).
// Epilogue: min/max atomics + flagged candidate extraction. No sim matrix.
// ---------------------------------------------------------------------------
#define STG_BYTES 32768
#define SMEM_GEMM 67584
#define SCUT 0.22f   // BASE - 14/BETA: provable negative-drop threshold

__global__ void __launch_bounds__(256, 2) gemm_kernel(const int* __restrict__ labels) {
    const int t = blockIdx.x;
    int bi = (int)((129.0 - sqrt(16641.0 - 8.0 * (double)t)) * 0.5);
    while ((bi + 1) * 64 - ((bi + 1) * bi) / 2 <= t) bi++;
    while (bi * 64 - (bi * (bi - 1)) / 2 > t) bi--;
    const int bj = bi + (t - (bi * 64 - (bi * (bi - 1)) / 2));

    extern __shared__ __align__(16) char smem[];
    uint32_t sb = smem_u32(smem);
    const int tid = threadIdx.x, lane = tid & 31, wid = tid >> 5;
    const int mwarp = (wid >> 2) * 64, nwarp = (wid & 3) * 32;
    const int r0 = bi * 128, c0 = bj * 128;
    const unsigned char* __restrict__ embA = d_embq + (size_t)r0 * ND;
    const unsigned char* __restrict__ embB = d_embq + (size_t)c0 * ND;

    int acc[4][4][4] = {};
    const int fRow = lane & 15;
    const int fCk = lane >> 4;

    // prologue: both K-stages (full K=256 int8 = 2 x 128B per row)
#pragma unroll
    for (int s = 0; s < 2; s++) {
        uint32_t base = sb + s * STG_BYTES;
#pragma unroll
        for (int it = 0; it < 4; it++) {
            int task = it * 256 + tid;
            int r = task >> 3, c = task & 7;
            cp16(base + r * 128 + ((c ^ (r & 7)) << 4), embA + r * ND + s * 128 + c * 16);
        }
#pragma unroll
        for (int it = 0; it < 4; it++) {
            int task = it * 256 + tid;
            int r = task >> 3, c = task & 7;
            cp16(base + 16384 + r * 128 + ((c ^ (r & 7)) << 4), embB + r * ND + s * 128 + c * 16);
        }
        cp_commit();
    }

#pragma unroll
    for (int s = 0; s < 2; s++) {
        if (s == 0) cp_wait<1>(); else cp_wait<0>();
        __syncthreads();
        uint32_t sA = sb + s * STG_BYTES + mwarp * 128;
        uint32_t sB = sb + s * STG_BYTES + 16384 + nwarp * 128;
#pragma unroll
        for (int ks = 0; ks < 4; ks++) {  // 4 x k32 = 128 int8
            uint32_t a[4][4], b[2][4];
#pragma unroll
            for (int mf = 0; mf < 4; mf++) {
                int row = mf * 16 + fRow;
                ldsm4(a[mf], sA + row * 128 + (((ks * 2 + fCk) ^ (row & 7)) << 4));
            }
#pragma unroll
            for (int nf2 = 0; nf2 < 2; nf2++) {
                int row = nf2 * 16 + fRow;
                ldsm4(b[nf2], sB + row * 128 + (((ks * 2 + fCk) ^ (row & 7)) << 4));
            }
#pragma unroll
            for (int mf = 0; mf < 4; mf++)
#pragma unroll
                for (int nf = 0; nf < 4; nf++)
                    mma32s8(acc[mf][nf], a[mf],
                            b[nf >> 1][nf & 1], b[nf >> 1][(nf & 1) + 2]);
        }
    }
    __syncthreads();   // all warps done reading stage smem before Cbuf overwrite

    // Epilogue: fp32 C tile in smem (stride 129), labels in smem.
    const float mx = __uint_as_float(d_maxabs);
    const float invS2 = (mx * mx) / (127.0f * 127.0f);
    float* Cbuf = (float*)smem;           // 66048 B
    int* rlab = (int*)(smem + 66304);
    int* clab = rlab + 128;
#pragma unroll
    for (int mf = 0; mf < 4; mf++) {
        int rb = mwarp + mf * 16 + (lane >> 2);
#pragma unroll
        for (int nf = 0; nf < 4; nf++) {
            int cb = nwarp + nf * 8 + 2 * (lane & 3);
            Cbuf[rb * 129 + cb]       = (float)acc[mf][nf][0] * invS2;
            Cbuf[rb * 129 + cb + 1]   = (float)acc[mf][nf][1] * invS2;
            Cbuf[(rb + 8) * 129 + cb]     = (float)acc[mf][nf][2] * invS2;
            Cbuf[(rb + 8) * 129 + cb + 1] = (float)acc[mf][nf][3] * invS2;
        }
    }
    if (tid < 128) rlab[tid] = labels[r0 + tid];
    else clab[tid - 128] = labels[c0 + tid - 128];
    __syncthreads();

    // Row-side: masked min/max + candidate extraction (2 threads per row).
    {
        int r = tid >> 1, half = tid & 1;
        int gi = r0 + r, li = rlab[r];
        float pmin = INFINITY, nmax = -INFINITY;
        for (int c = half * 64; c < half * 64 + 64; c++) {
            float s = Cbuf[r * 129 + c];
            int gj = c0 + c;
            if (clab[c] == li) {
                if (gj != gi) {
                    pmin = fminf(pmin, s);
                    push_cand(gi, gj, s, false);
                }
            } else {
                nmax = fmaxf(nmax, s);
                if (s > SCUT) push_cand(gi, gj, s, true);
            }
        }
        pmin = fminf(pmin, __shfl_xor_sync(0xFFFFFFFFu, pmin, 1));
        nmax = fmaxf(nmax, __shfl_xor_sync(0xFFFFFFFFu, nmax, 1));
        if (half == 0) {
            if (pmin < INFINITY) atomicMin(&d_rmin[gi], encf(pmin));
            if (nmax > -INFINITY) atomicMax(&d_rmax[gi], encf(nmax));
        }
    }
    // Col-side (transpose contribution).
    if (bi != bj) {
        int c = tid >> 1, half = tid & 1;
        int gj = c0 + c, lj = clab[c];
        float pmin = INFINITY, nmax = -INFINITY;
        for (int r = half * 64; r < half * 64 + 64; r++) {
            float s = Cbuf[r * 129 + c];
            int gi2 = r0 + r;
            if (rlab[r] == lj) {
                pmin = fminf(pmin, s);
                push_cand(gj, gi2, s, false);
            } else {
                nmax = fmaxf(nmax, s);
                if (s > SCUT) push_cand(gj, gi2, s, true);
            }
        }
        pmin = fminf(pmin, __shfl_xor_sync(0xFFFFFFFFu, pmin, 1));
        nmax = fmaxf(nmax, __shfl_xor_sync(0xFFFFFFFFu, nmax, 1));
        if (half == 0) {
            if (pmin < INFINITY) atomicMin(&d_rmin[gj], encf(pmin));
            if (nmax > -INFINITY) atomicMax(&d_rmax[gj], encf(nmax));
        }
    }
}

// ---------------------------------------------------------------------------
// Row kernel: one thread per row. Vector-load candidates, sort by key
// (flag|j -> deterministic order), tiny exp sums. No label loads.
// ---------------------------------------------------------------------------
__global__ void __launch_bounds__(128) row_kernel() {
    const int i = blockIdx.x * 128 + threadIdx.x;
    const float ALPHA = 2.0f, BETA = 50.0f, BASE = 0.5f, MARGIN = 0.1f;
    const float L2E = 1.44269504f;

    float pmin = decf(d_rmin[i]);
    float nmax = decf(d_rmax[i]);

    bool anyP = (pmin - MARGIN < nmax);
    bool anyN = (nmax + MARGIN > pmin);
    if (!(anyP && anyN)) {
        d_row_term[i] = 0.0f;
        d_row_valid[i] = 0.0f;
        return;
    }

    float m_pos = fmaxf(-ALPHA * (pmin - BASE), 0.0f);
    float m_neg = fmaxf(BETA * (nmax - BASE), 0.0f);

    const float kn1 = BETA * L2E;
    const float kn0 = (-BETA * BASE - m_neg) * L2E;
    const float kp1 = -ALPHA * L2E;
    const float kp0 = (ALPHA * BASE - m_pos) * L2E;
    const float thrN = pmin - MARGIN;
    const float thrP = nmax + MARGIN;

    int n = d_cnt[i];
    if (n > MAXC) n = MAXC;

    unsigned int keys[MAXC];
    const uint4* src = (const uint4*)&d_cand[(size_t)i * MAXC];
    // batched vector loads (parallel in flight), then insertion sort
    for (int k4 = 0; k4 * 4 < n; k4++) {
        uint4 v = src[k4];
        unsigned int kv[4] = {v.x, v.y, v.z, v.w};
#pragma unroll
        for (int e = 0; e < 4; e++) {
            int k = k4 * 4 + e;
            if (k < n) {
                unsigned int key = kv[e];
                int b = k - 1;
                while (b >= 0 && keys[b] > key) {
                    keys[b + 1] = keys[b];
                    b--;
                }
                keys[b + 1] = key;
            }
        }
    }

    float sp = 0.0f, sn = 0.0f;
    for (int k = 0; k < n; k++) {
        unsigned int key = keys[k];
        float s = __half2float(__ushort_as_half((unsigned short)(key & 0xFFFFu)));
        if (key & 0x80000000u) {
            if (s > thrN) sn += ex2(fmaf(kn1, s, kn0));
        } else {
            if (s < thrP) sp += ex2(fmaf(kp1, s, kp0));
        }
    }

    float pt = (logf(expf(-m_pos) + sp) + m_pos) / ALPHA;
    float nt = (logf(expf(-m_neg) + sn) + m_neg) / BETA;
    d_row_term[i] = pt + nt;
    d_row_valid[i] = 1.0f;
}

__global__ void __launch_bounds__(1024) final_kernel(float* __restrict__ out) {
    const int tid = threadIdx.x;
    float t = 0.0f, v = 0.0f;
    for (int j = tid; j < NB; j += 1024) {
        t += d_row_term[j];
        v += d_row_valid[j];
    }
    __shared__ float rt[1024], rv[1024];
    rt[tid] = t; rv[tid] = v;
    __syncthreads();
    for (int o = 512; o > 0; o >>= 1) {
        if (tid < o) { rt[tid] += rt[tid + o]; rv[tid] += rv[tid + o]; }
        __syncthreads();
    }
    if (tid == 0) out[0] = rt[0] / fmaxf(rv[0], 1.0f);
}

extern "C" void kernel_launch(void* const* d_in, const int* in_sizes, int n_in,
                              void* d_out, int out_size) {
    const float* emb = (const float*)d_in[0];
    const int* labels = (const int*)d_in[1];
    float* out = (float*)d_out;

    cudaFuncSetAttribute(gemm_kernel, cudaFuncAttributeMaxDynamicSharedMemorySize, SMEM_GEMM);

    prep_misc<<<NB / 256, 256>>>(labels);
    prep_max<<<(NB * ND / 8) / 256, 256>>>(emb);
    prep_quant<<<(NB * ND / 8) / 256, 256>>>(emb);
    gemm_kernel<<<2080, 256, SMEM_GEMM>>>(labels);
    row_kernel<<<NB / 128, 128>>>();
    final_kernel<<<1, 1024>>>(out);
}

// round 12
// speedup vs baseline: 1.3212x; 1.3212x over previous
#include <cuda_runtime.h>
#include <cuda_fp16.h>
#include <math.h>
#include <stdint.h>

#define NB 8192
#define ND 256
#define MAXC 64    // per-row candidate capacity (expected ~10, max ~35)

__device__ __half d_embh[(size_t)NB * ND];     // 4 MB
__device__ unsigned int d_rmin[NB];
__device__ unsigned int d_rmax[NB];
__device__ unsigned int d_cand[(size_t)NB * MAXC];  // bit31=neg | j<<16 | f16bits(s)
__device__ int d_cnt[NB];
__device__ float d_sum, d_vld;

// ---------------- helpers ----------------
__device__ __forceinline__ uint32_t smem_u32(const void* p) {
    uint32_t a;
    asm("{ .reg .u64 t; cvta.to.shared.u64 t, %1; cvt.u32.u64 %0, t; }" : "=r"(a) : "l"(p));
    return a;
}
__device__ __forceinline__ void cp16(uint32_t dst, const void* src) {
    asm volatile("cp.async.cg.shared.global [%0], [%1], 16;" :: "r"(dst), "l"(src) : "memory");
}
__device__ __forceinline__ void cp_commit() {
    asm volatile("cp.async.commit_group;" ::: "memory");
}
template <int N>
__device__ __forceinline__ void cp_wait() {
    asm volatile("cp.async.wait_group %0;" :: "n"(N) : "memory");
}
__device__ __forceinline__ void cp_wait_n(int n) {
    if (n == 0) cp_wait<0>();
    else if (n == 1) cp_wait<1>();
    else cp_wait<2>();
}
__device__ __forceinline__ void ldsm4(uint32_t r[4], uint32_t addr) {
    asm volatile("ldmatrix.sync.aligned.m8n8.x4.shared.b16 {%0,%1,%2,%3}, [%4];"
                 : "=r"(r[0]), "=r"(r[1]), "=r"(r[2]), "=r"(r[3]) : "r"(addr));
}
__device__ __forceinline__ void mma16h(uint32_t c[2], const uint32_t a[4], uint32_t b0, uint32_t b1) {
    asm volatile(
        "mma.sync.aligned.m16n8k16.row.col.f16.f16.f16.f16 "
        "{%0,%1}, {%2,%3,%4,%5}, {%6,%7}, {%0,%1};"
        : "+r"(c[0]), "+r"(c[1])
        : "r"(a[0]), "r"(a[1]), "r"(a[2]), "r"(a[3]), "r"(b0), "r"(b1));
}
__device__ __forceinline__ float ex2(float x) {
    float r;
    asm("ex2.approx.f32 %0, %1;" : "=f"(r) : "f"(x));
    return r;
}
__device__ __forceinline__ unsigned int encf(float f) {
    unsigned int u = __float_as_uint(f);
    return (u >> 31) ? ~u : (u | 0x80000000u);
}
__device__ __forceinline__ float decf(unsigned int u) {
    return __uint_as_float((u >> 31) ? (u ^ 0x80000000u) : ~u);
}
__device__ __forceinline__ void push_cand(int row, int j, float s, bool isneg) {
    unsigned int key = (isneg ? 0x80000000u : 0u) | ((unsigned)j << 16)
                     | (unsigned)__half_as_ushort(__float2half_rn(s));
    int p = atomicAdd(&d_cnt[row], 1);
    if (p < MAXC) d_cand[(size_t)row * MAXC + p] = key;
}

// ---------------------------------------------------------------------------
// Prep: emb -> f16 + init arrays (fused).
// ---------------------------------------------------------------------------
__global__ void __launch_bounds__(256) prep_emb(const float* __restrict__ emb) {
    int i = blockIdx.x * 256 + threadIdx.x;
    float4 v0 = ((const float4*)emb)[i * 2];
    float4 v1 = ((const float4*)emb)[i * 2 + 1];
    __half2 h[4];
    h[0] = __float22half2_rn(make_float2(v0.x, v0.y));
    h[1] = __float22half2_rn(make_float2(v0.z, v0.w));
    h[2] = __float22half2_rn(make_float2(v1.x, v1.y));
    h[3] = __float22half2_rn(make_float2(v1.z, v1.w));
    ((uint4*)d_embh)[i] = *(uint4*)h;
    if (i < NB) {
        d_rmin[i] = 0xFFFFFFFFu;
        d_rmax[i] = 0u;
        d_cnt[i] = 0;
    }
    if (i == 0) { d_sum = 0.0f; d_vld = 0.0f; }
}

// ---------------------------------------------------------------------------
// GEMM: f16 mma.sync m16n8k16, triangular 128x128 tiles, 8 warps of 64x32,
// BK=64, 3-stage cp.async, fragment double-buffering.
// Epilogue: min/max atomics + flagged candidate extraction. No sim matrix.
// ---------------------------------------------------------------------------
#define STG_BYTES 32768
#define SMEM_GEMM 98304
#define SCUT 0.22f   // BASE - 14/BETA: provable negative-drop threshold

__global__ void __launch_bounds__(256, 2) gemm_kernel(const int* __restrict__ labels) {
    const int t = blockIdx.x;
    int bi = (int)((129.0 - sqrt(16641.0 - 8.0 * (double)t)) * 0.5);
    while ((bi + 1) * 64 - ((bi + 1) * bi) / 2 <= t) bi++;
    while (bi * 64 - (bi * (bi - 1)) / 2 > t) bi--;
    const int bj = bi + (t - (bi * 64 - (bi * (bi - 1)) / 2));

    extern __shared__ __align__(16) char smem[];
    uint32_t sb = smem_u32(smem);
    const int tid = threadIdx.x, lane = tid & 31, wid = tid >> 5;
    const int mwarp = (wid >> 2) * 64, nwarp = (wid & 3) * 32;
    const int r0 = bi * 128, c0 = bj * 128;
    const __half* __restrict__ embA = d_embh + (size_t)r0 * ND;
    const __half* __restrict__ embB = d_embh + (size_t)c0 * ND;

    uint32_t acc[4][4][2] = {};
    const int fRow = lane & 15;
    const int fCk = lane >> 4;

    auto load_stage = [&](int s) {
        uint32_t base = sb + (s % 3) * STG_BYTES;
        int k0 = s * 64;
#pragma unroll
        for (int it = 0; it < 4; it++) {
            int task = it * 256 + tid;
            int r = task >> 3, c = task & 7;
            cp16(base + r * 128 + ((c ^ (r & 7)) << 4),
                 embA + (size_t)r * ND + k0 + c * 8);
        }
#pragma unroll
        for (int it = 0; it < 4; it++) {
            int task = it * 256 + tid;
            int r = task >> 3, c = task & 7;
            cp16(base + 16384 + r * 128 + ((c ^ (r & 7)) << 4),
                 embB + (size_t)r * ND + k0 + c * 8);
        }
        cp_commit();
    };

    load_stage(0);
    load_stage(1);
    load_stage(2);

    for (int s = 0; s < 4; s++) {
        int pend = 3 - s;
        cp_wait_n(pend < 2 ? pend : 2);
        __syncthreads();
        uint32_t sA = sb + (s % 3) * STG_BYTES + mwarp * 128;
        uint32_t sB = sb + (s % 3) * STG_BYTES + 16384 + nwarp * 128;

        uint32_t a[2][4][4], b[2][2][4];
        auto ldfrag = [&](int ks, int buf) {
#pragma unroll
            for (int mf = 0; mf < 4; mf++) {
                int row = mf * 16 + fRow;
                ldsm4(a[buf][mf], sA + row * 128 + (((ks * 2 + fCk) ^ (row & 7)) << 4));
            }
#pragma unroll
            for (int nf2 = 0; nf2 < 2; nf2++) {
                int row = nf2 * 16 + fRow;
                ldsm4(b[buf][nf2], sB + row * 128 + (((ks * 2 + fCk) ^ (row & 7)) << 4));
            }
        };
        ldfrag(0, 0);
#pragma unroll
        for (int ks = 0; ks < 4; ks++) {
            int cur = ks & 1;
            if (ks < 3) ldfrag(ks + 1, cur ^ 1);
#pragma unroll
            for (int mf = 0; mf < 4; mf++)
#pragma unroll
                for (int nf = 0; nf < 4; nf++)
                    mma16h(acc[mf][nf], a[cur][mf],
                           b[cur][nf >> 1][nf & 1], b[cur][nf >> 1][(nf & 1) + 2]);
        }
        __syncthreads();
        if (s + 3 < 4) load_stage(s + 3);
    }

    // Epilogue: fp32 C tile in smem (stride 129), labels in smem.
    float* Cbuf = (float*)smem;
    int* rlab = (int*)(smem + 66304);
    int* clab = rlab + 128;
#pragma unroll
    for (int mf = 0; mf < 4; mf++) {
        int rb = mwarp + mf * 16 + (lane >> 2);
#pragma unroll
        for (int nf = 0; nf < 4; nf++) {
            int cb = nwarp + nf * 8 + 2 * (lane & 3);
            float2 v0 = __half22float2(*(__half2*)&acc[mf][nf][0]);
            float2 v1 = __half22float2(*(__half2*)&acc[mf][nf][1]);
            Cbuf[rb * 129 + cb] = v0.x;
            Cbuf[rb * 129 + cb + 1] = v0.y;
            Cbuf[(rb + 8) * 129 + cb] = v1.x;
            Cbuf[(rb + 8) * 129 + cb + 1] = v1.y;
        }
    }
    if (tid < 128) rlab[tid] = labels[r0 + tid];
    else clab[tid - 128] = labels[c0 + tid - 128];
    __syncthreads();

    // Row-side: masked min/max + candidate extraction (2 threads per row).
    {
        int r = tid >> 1, half = tid & 1;
        int gi = r0 + r, li = rlab[r];
        float pmin = INFINITY, nmax = -INFINITY;
        for (int c = half * 64; c < half * 64 + 64; c++) {
            float s = Cbuf[r * 129 + c];
            int gj = c0 + c;
            if (clab[c] == li) {
                if (gj != gi) {
                    pmin = fminf(pmin, s);
                    push_cand(gi, gj, s, false);
                }
            } else {
                nmax = fmaxf(nmax, s);
                if (s > SCUT) push_cand(gi, gj, s, true);
            }
        }
        pmin = fminf(pmin, __shfl_xor_sync(0xFFFFFFFFu, pmin, 1));
        nmax = fmaxf(nmax, __shfl_xor_sync(0xFFFFFFFFu, nmax, 1));
        if (half == 0) {
            if (pmin < INFINITY) atomicMin(&d_rmin[gi], encf(pmin));
            if (nmax > -INFINITY) atomicMax(&d_rmax[gi], encf(nmax));
        }
    }
    // Col-side (transpose contribution).
    if (bi != bj) {
        int c = tid >> 1, half = tid & 1;
        int gj = c0 + c, lj = clab[c];
        float pmin = INFINITY, nmax = -INFINITY;
        for (int r = half * 64; r < half * 64 + 64; r++) {
            float s = Cbuf[r * 129 + c];
            int gi2 = r0 + r;
            if (rlab[r] == lj) {
                pmin = fminf(pmin, s);
                push_cand(gj, gi2, s, false);
            } else {
                nmax = fmaxf(nmax, s);
                if (s > SCUT) push_cand(gj, gi2, s, true);
            }
        }
        pmin = fminf(pmin, __shfl_xor_sync(0xFFFFFFFFu, pmin, 1));
        nmax = fmaxf(nmax, __shfl_xor_sync(0xFFFFFFFFu, nmax, 1));
        if (half == 0) {
            if (pmin < INFINITY) atomicMin(&d_rmin[gj], encf(pmin));
            if (nmax > -INFINITY) atomicMax(&d_rmax[gj], encf(nmax));
        }
    }
}

// ---------------------------------------------------------------------------
// Row kernel: one thread per row, flag-encoded candidates (no label loads),
// block-reduced atomicAdd into global sum/valid.
// ---------------------------------------------------------------------------
__global__ void __launch_bounds__(128) row_kernel() {
    const int i = blockIdx.x * 128 + threadIdx.x;
    const float ALPHA = 2.0f, BETA = 50.0f, BASE = 0.5f, MARGIN = 0.1f;
    const float L2E = 1.44269504f;

    float pmin = decf(d_rmin[i]);
    float nmax = decf(d_rmax[i]);

    float term = 0.0f, valid = 0.0f;
    bool anyP = (pmin - MARGIN < nmax);
    bool anyN = (nmax + MARGIN > pmin);
    if (anyP && anyN) {
        float m_pos = fmaxf(-ALPHA * (pmin - BASE), 0.0f);
        float m_neg = fmaxf(BETA * (nmax - BASE), 0.0f);

        const float kn1 = BETA * L2E;
        const float kn0 = (-BETA * BASE - m_neg) * L2E;
        const float kp1 = -ALPHA * L2E;
        const float kp0 = (ALPHA * BASE - m_pos) * L2E;
        const float thrN = pmin - MARGIN;
        const float thrP = nmax + MARGIN;

        int n = d_cnt[i];
        if (n > MAXC) n = MAXC;

        unsigned int keys[MAXC];
        const uint4* src = (const uint4*)&d_cand[(size_t)i * MAXC];
        for (int k4 = 0; k4 * 4 < n; k4++) {
            uint4 v = src[k4];
            unsigned int kv[4] = {v.x, v.y, v.z, v.w};
#pragma unroll
            for (int e = 0; e < 4; e++) {
                int k = k4 * 4 + e;
                if (k < n) {
                    unsigned int key = kv[e];
                    int b = k - 1;
                    while (b >= 0 && keys[b] > key) {
                        keys[b + 1] = keys[b];
                        b--;
                    }
                    keys[b + 1] = key;
                }
            }
        }

        float sp = 0.0f, sn = 0.0f;
        for (int k = 0; k < n; k++) {
            unsigned int key = keys[k];
            float s = __half2float(__ushort_as_half((unsigned short)(key & 0xFFFFu)));
            if (key & 0x80000000u) {
                if (s > thrN) sn += ex2(fmaf(kn1, s, kn0));
            } else {
                if (s < thrP) sp += ex2(fmaf(kp1, s, kp0));
            }
        }

        float pt = (logf(expf(-m_pos) + sp) + m_pos) / ALPHA;
        float nt = (logf(expf(-m_neg) + sn) + m_neg) / BETA;
        term = pt + nt;
        valid = 1.0f;
    }

    __shared__ float rt[128], rv[128];
    int tid = threadIdx.x;
    rt[tid] = term;
    rv[tid] = valid;
    __syncthreads();
    for (int o = 64; o > 0; o >>= 1) {
        if (tid < o) { rt[tid] += rt[tid + o]; rv[tid] += rv[tid + o]; }
        __syncthreads();
    }
    if (tid == 0) {
        atomicAdd(&d_sum, rt[0]);
        atomicAdd(&d_vld, rv[0]);
    }
}

__global__ void final_kernel(float* __restrict__ out) {
    out[0] = d_sum / fmaxf(d_vld, 1.0f);
}

extern "C" void kernel_launch(void* const* d_in, const int* in_sizes, int n_in,
                              void* d_out, int out_size) {
    const float* emb = (const float*)d_in[0];
    const int* labels = (const int*)d_in[1];
    float* out = (float*)d_out;

    cudaFuncSetAttribute(gemm_kernel, cudaFuncAttributeMaxDynamicSharedMemorySize, SMEM_GEMM);

    prep_emb<<<(NB * ND / 8) / 256, 256>>>(emb);
    gemm_kernel<<<2080, 256, SMEM_GEMM>>>(labels);
    row_kernel<<<NB / 128, 128>>>();
    final_kernel<<<1, 1>>>(out);
}